// round 7
// baseline (speedup 1.0000x reference)
#include <cuda_runtime.h>
#include <math.h>

#define NPTS 262144
#define HID 128
#define CTXD 128
#define NSTEPS 50
#define ZD 2
#define AS_LD 129   // odd stride -> conflict-free scalar smem access

// output layout: traj (51,N,2) | us (50,N,2) | times (51)
#define OUT_US    ((size_t)(NSTEPS + 1) * NPTS * ZD)
#define OUT_TIMES (OUT_US + (size_t)NSTEPS * NPTS * ZD)

__device__ float g_dctx[NPTS * HID];   // posterior_ctx @ dW1[2:130] + db1
__device__ float g_cctx[NPTS * HID];   // cnf_ctx @ cW1[2:130] + cb1
__device__ float g_tvd[NSTEPS * HID];  // temb @ dW1[130:162]
__device__ float g_tvc[NSTEPS * HID];
__device__ float g_dt[NSTEPS];
__device__ float g_gs[NSTEPS];         // g_base*(1-t_i)*sqrt(max(dt,1e-12))

__device__ __forceinline__ float siluf(float x) {
    return __fdividef(x, 1.0f + __expf(-x));
}

// 64x128 @ 128x128 register-tiled GEMM core using packed fp32x2 FMA.
// Thread tile: 4 rows x 8 cols (4 f32x2 pairs).
__device__ __forceinline__ void gemm_core(const float* __restrict__ As,
                                          const float* __restrict__ Ws,
                                          int r0, int c0,
                                          unsigned long long (&acc)[4][4]) {
#pragma unroll
    for (int i = 0; i < 4; ++i)
#pragma unroll
        for (int j = 0; j < 4; ++j) acc[i][j] = 0ull;

#pragma unroll 4
    for (int k = 0; k < HID; ++k) {
        unsigned long long h[4];
#pragma unroll
        for (int i = 0; i < 4; ++i) {
            unsigned v = __float_as_uint(As[(r0 + i) * AS_LD + k]);
            asm("mov.b64 %0, {%1, %1};" : "=l"(h[i]) : "r"(v));
        }
        const float* wr = Ws + k * HID + c0;
        ulonglong2 wa = *(const ulonglong2*)(wr);       // LDS.128
        ulonglong2 wb = *(const ulonglong2*)(wr + 4);
        unsigned long long w0 = wa.x, w1 = wa.y, w2 = wb.x, w3 = wb.y;
#pragma unroll
        for (int i = 0; i < 4; ++i) {
            asm("fma.rn.f32x2 %0, %1, %2, %0;" : "+l"(acc[i][0]) : "l"(h[i]), "l"(w0));
            asm("fma.rn.f32x2 %0, %1, %2, %0;" : "+l"(acc[i][1]) : "l"(h[i]), "l"(w1));
            asm("fma.rn.f32x2 %0, %1, %2, %0;" : "+l"(acc[i][2]) : "l"(h[i]), "l"(w2));
            asm("fma.rn.f32x2 %0, %1, %2, %0;" : "+l"(acc[i][3]) : "l"(h[i]), "l"(w3));
        }
    }
}

// ---------------- precompute: ctx @ W1[2:130] + b1 ----------------
__global__ void __launch_bounds__(256, 2)
ctx_kernel(const float* __restrict__ X, const float* __restrict__ W1,
           const float* __restrict__ b1, int which) {
    extern __shared__ float sm[];
    float* Ws = sm;               // 128*128
    float* Xs = sm + HID * HID;   // 64*AS_LD
    float* out = which ? g_cctx : g_dctx;
    int tid = threadIdx.x;
    size_t row0 = (size_t)blockIdx.x * 64;

    for (int i = tid; i < HID * HID; i += 256) Ws[i] = W1[2 * HID + i];
#pragma unroll 4
    for (int i = tid; i < 64 * HID; i += 256) {
        int r = i >> 7, c = i & 127;
        Xs[r * AS_LD + c] = X[(row0 + r) * HID + c];
    }
    __syncthreads();

    int rg = tid >> 4, cg = tid & 15;
    int r0 = rg * 4, c0 = cg * 8;
    unsigned long long acc[4][4];
    gemm_core(Xs, Ws, r0, c0, acc);

#pragma unroll
    for (int i = 0; i < 4; ++i) {
        size_t base = (row0 + r0 + i) * HID + c0;
#pragma unroll
        for (int j = 0; j < 4; ++j) {
            unsigned lo, hi;
            asm("mov.b64 {%0, %1}, %2;" : "=r"(lo), "=r"(hi) : "l"(acc[i][j]));
            float2 v;
            v.x = __uint_as_float(lo) + b1[c0 + 2 * j];
            v.y = __uint_as_float(hi) + b1[c0 + 2 * j + 1];
            *(float2*)&out[base + 2 * j] = v;
        }
    }
}

// ---------------- per-step constants (tiny) ----------------
__global__ void __launch_bounds__(128)
step_const_kernel(const float* __restrict__ times, const float* __restrict__ freqs,
                  const float* __restrict__ dW1, const float* __restrict__ cW1,
                  const float* __restrict__ logd, float* __restrict__ out) {
    int s = blockIdx.x;
    int t = threadIdx.x;
    __shared__ float temb[32];
    float t_i = times[s];
    if (t < 32) {
        float a = 6.28318530717958647692f * t_i * freqs[t & 15];
        temb[t] = (t < 16) ? sinf(a) : cosf(a);
    }
    __syncthreads();
    if (t < HID) {
        float sd = 0.0f, sc = 0.0f;
#pragma unroll
        for (int k = 0; k < 32; ++k) {
            sd += temb[k] * dW1[(2 + CTXD + k) * HID + t];
            sc += temb[k] * cW1[(2 + CTXD + k) * HID + t];
        }
        g_tvd[s * HID + t] = sd;
        g_tvc[s * HID + t] = sc;
    }
    if (t == 0) {
        float dt = times[s + 1] - t_i;
        float gb = log1pf(expf(logd[0]));   // softplus, DIFFUSION_SCALE=1
        g_dt[s] = dt;
        g_gs[s] = gb * (1.0f - t_i) * sqrtf(fmaxf(dt, 1e-12f));
    }
    if (s == 0 && t < NSTEPS + 1) out[OUT_TIMES + t] = times[t];
}

// ---------------- main: 50-step SDE loop, 64 rows per CTA ----------------
__global__ void __launch_bounds__(256, 1)
sde_kernel(const float* __restrict__ z0, const float* __restrict__ noise,
           const float* __restrict__ dW1, const float* __restrict__ dW2,
           const float* __restrict__ db2, const float* __restrict__ dW3,
           const float* __restrict__ db3,
           const float* __restrict__ cW1, const float* __restrict__ cW2,
           const float* __restrict__ cb2, const float* __restrict__ cW3,
           const float* __restrict__ cb3,
           float* __restrict__ out) {
    extern __shared__ float sm[];
    float* W2ds = sm;                       // 16384
    float* W2cs = W2ds + HID * HID;         // 16384
    float* As   = W2cs + HID * HID;         // 64*129
    float* Bs   = As + 64 * AS_LD;          // 64*129
    float* w1zd = Bs + 64 * AS_LD;          // 256 (dW1 rows 0..1)
    float* w1zc = w1zd + 256;               // 256
    float* w3ds = w1zc + 256;               // 256 (dW3 [128][2])
    float* w3cs = w3ds + 256;               // 256
    float* b2ds = w3cs + 256;               // 128
    float* b2cs = b2ds + 128;               // 128
    float* tvds = b2cs + 128;               // 128
    float* tvcs = tvds + 128;               // 128
    float* zsm  = tvcs + 128;               // 128 (64 rows x 2)
    float* b3s  = zsm + 128;                // 4

    int tid = threadIdx.x;
    size_t row0 = (size_t)blockIdx.x * 64;

    for (int i = tid; i < HID * HID; i += 256) { W2ds[i] = dW2[i]; W2cs[i] = cW2[i]; }
    w1zd[tid] = dW1[tid]; w1zc[tid] = cW1[tid];
    w3ds[tid] = dW3[tid]; w3cs[tid] = cW3[tid];
    if (tid < 128) { b2ds[tid] = db2[tid]; b2cs[tid] = cb2[tid]; }
    if (tid < 2)   { b3s[tid] = db3[tid];  b3s[2 + tid] = cb3[tid]; }
    if (tid < 128) {
        float zv = z0[row0 * 2 + tid];
        zsm[tid] = zv;
        out[row0 * 2 + tid] = zv;           // traj[0] = z0
    }
    __syncthreads();

    int rg = tid >> 4, cg = tid & 15;
    int r0 = rg * 4, c0 = cg * 8;

    for (int s = 0; s < NSTEPS; ++s) {
        if (tid < 128) tvds[tid] = g_tvd[s * HID + tid];
        else           tvcs[tid - 128] = g_tvc[s * HID + tid - 128];
        float dt  = g_dt[s];
        float gsc = g_gs[s];
        __syncthreads();

        // layer1, diffusion net -> As
#pragma unroll 8
        for (int i = tid; i < 64 * HID; i += 256) {
            int r = i >> 7, c = i & 127;
            float x = g_dctx[(row0 + r) * HID + c] + tvds[c]
                    + zsm[r * 2] * w1zd[c] + zsm[r * 2 + 1] * w1zd[HID + c];
            As[r * AS_LD + c] = siluf(x);
        }
        __syncthreads();

        // layer2, diffusion: Bs = silu(As @ W2d + db2)
        unsigned long long acc[4][4];
        gemm_core(As, W2ds, r0, c0, acc);
#pragma unroll
        for (int i = 0; i < 4; ++i)
#pragma unroll
            for (int j = 0; j < 4; ++j) {
                unsigned lo, hi;
                asm("mov.b64 {%0, %1}, %2;" : "=r"(lo), "=r"(hi) : "l"(acc[i][j]));
                Bs[(r0 + i) * AS_LD + c0 + 2 * j]     = siluf(__uint_as_float(lo) + b2ds[c0 + 2 * j]);
                Bs[(r0 + i) * AS_LD + c0 + 2 * j + 1] = siluf(__uint_as_float(hi) + b2ds[c0 + 2 * j + 1]);
            }
        __syncthreads();

        // layer1, cnf net -> As (overwrite)
#pragma unroll 8
        for (int i = tid; i < 64 * HID; i += 256) {
            int r = i >> 7, c = i & 127;
            float x = g_cctx[(row0 + r) * HID + c] + tvcs[c]
                    + zsm[r * 2] * w1zc[c] + zsm[r * 2 + 1] * w1zc[HID + c];
            As[r * AS_LD + c] = siluf(x);
        }
        __syncthreads();

        // layer2, cnf: As = silu(As @ W2c + cb2)  (read all, sync, write in place)
        gemm_core(As, W2cs, r0, c0, acc);
        __syncthreads();
#pragma unroll
        for (int i = 0; i < 4; ++i)
#pragma unroll
            for (int j = 0; j < 4; ++j) {
                unsigned lo, hi;
                asm("mov.b64 {%0, %1}, %2;" : "=r"(lo), "=r"(hi) : "l"(acc[i][j]));
                As[(r0 + i) * AS_LD + c0 + 2 * j]     = siluf(__uint_as_float(lo) + b2cs[c0 + 2 * j]);
                As[(r0 + i) * AS_LD + c0 + 2 * j + 1] = siluf(__uint_as_float(hi) + b2cs[c0 + 2 * j + 1]);
            }
        __syncthreads();

        // layer3 + SDE update: one thread per (row, dim)
        if (tid < 128) {
            int r = tid >> 1, d = tid & 1;
            float au = b3s[d], af = b3s[2 + d];
#pragma unroll 8
            for (int j = 0; j < HID; ++j) {
                au += Bs[r * AS_LD + j] * w3ds[j * 2 + d];   // u (diffusion)
                af += As[r * AS_LD + j] * w3cs[j * 2 + d];   // f_theta (cnf)
            }
            size_t gi = row0 * 2 + tid;
            float xi = noise[(size_t)s * ((size_t)NPTS * ZD) + gi];
            float zn = zsm[tid] + (af + au) * dt + xi * gsc;
            out[OUT_US + (size_t)s * ((size_t)NPTS * ZD) + gi] = au;  // us[s]
            out[(size_t)(s + 1) * ((size_t)NPTS * ZD) + gi]    = zn;  // traj[s+1]
            zsm[tid] = zn;
        }
        // next-iteration leading __syncthreads gates all hazards
    }
}

extern "C" void kernel_launch(void* const* d_in, const int* in_sizes, int n_in,
                              void* d_out, int out_size) {
    (void)in_sizes; (void)n_in; (void)out_size;
    const float* z0    = (const float*)d_in[0];
    const float* pctx  = (const float*)d_in[1];
    const float* cctx  = (const float*)d_in[2];
    const float* times = (const float*)d_in[3];
    const float* noise = (const float*)d_in[4];
    const float* freqs = (const float*)d_in[5];
    const float* dW1   = (const float*)d_in[6];
    const float* db1   = (const float*)d_in[7];
    const float* dW2   = (const float*)d_in[8];
    const float* db2   = (const float*)d_in[9];
    const float* dW3   = (const float*)d_in[10];
    const float* db3   = (const float*)d_in[11];
    const float* cW1   = (const float*)d_in[12];
    const float* cb1   = (const float*)d_in[13];
    const float* cW2   = (const float*)d_in[14];
    const float* cb2   = (const float*)d_in[15];
    const float* cW3   = (const float*)d_in[16];
    const float* cb3   = (const float*)d_in[17];
    const float* logd  = (const float*)d_in[18];
    float* out = (float*)d_out;

    const int CTX_SMEM  = (HID * HID + 64 * AS_LD) * (int)sizeof(float);
    const int MAIN_SMEM = (2 * HID * HID + 2 * 64 * AS_LD + 4 * 256
                           + 2 * 128 + 2 * 128 + 128 + 8) * (int)sizeof(float);

    static int attr_done = 0;
    if (!attr_done) {
        cudaFuncSetAttribute(ctx_kernel, cudaFuncAttributeMaxDynamicSharedMemorySize, CTX_SMEM);
        cudaFuncSetAttribute(sde_kernel, cudaFuncAttributeMaxDynamicSharedMemorySize, MAIN_SMEM);
        attr_done = 1;
    }

    step_const_kernel<<<NSTEPS, 128>>>(times, freqs, dW1, cW1, logd, out);
    ctx_kernel<<<NPTS / 64, 256, CTX_SMEM>>>(pctx, dW1, db1, 0);
    ctx_kernel<<<NPTS / 64, 256, CTX_SMEM>>>(cctx, cW1, cb1, 1);
    sde_kernel<<<NPTS / 64, 256, MAIN_SMEM>>>(z0, noise, dW1, dW2, db2, dW3, db3,
                                              cW1, cW2, cb2, cW3, cb3, out);
}

// round 9
// speedup vs baseline: 3.1147x; 3.1147x over previous
#include <cuda_runtime.h>
#include <cuda_bf16.h>
#include <math.h>
#include <stdint.h>

#define NPTS 262144
#define HID 128
#define NSTEPS 50
#define AS_LD 129
#define ROWS 128
#define LDAW 68   // uint32 words per row (136 bf16) -> conflict-free frag loads

#define OUT_US    ((size_t)(NSTEPS + 1) * NPTS * 2)
#define OUT_TIMES (OUT_US + (size_t)NSTEPS * NPTS * 2)

__device__ float g_dctx[NPTS * HID];
__device__ float g_cctx[NPTS * HID];
__device__ float g_tvd[NSTEPS * HID];
__device__ float g_tvc[NSTEPS * HID];
__device__ float g_dt[NSTEPS];
__device__ float g_gs[NSTEPS];

__device__ __forceinline__ float siluf(float x) {
    return __fdividef(x, 1.0f + __expf(-x));
}

#define MMA(d, a, b) asm volatile( \
    "mma.sync.aligned.m16n8k16.row.col.f32.bf16.bf16.f32 " \
    "{%0,%1,%2,%3},{%4,%5,%6,%7},{%8,%9},{%0,%1,%2,%3};" \
    : "+f"((d)[0]), "+f"((d)[1]), "+f"((d)[2]), "+f"((d)[3]) \
    : "r"((a)[0]), "r"((a)[1]), "r"((a)[2]), "r"((a)[3]), "r"((b)[0]), "r"((b)[1]))

// ---------- FFMA2 GEMM (ctx precompute only, known-good from R6) ----------
__device__ __forceinline__ void gemm_core(const float* __restrict__ As,
                                          const float* __restrict__ Ws,
                                          int r0, int c0, unsigned long long (&acc)[4][4]) {
#pragma unroll
    for (int i = 0; i < 4; ++i)
#pragma unroll
        for (int j = 0; j < 4; ++j) acc[i][j] = 0ull;
#pragma unroll 4
    for (int k = 0; k < HID; ++k) {
        unsigned long long h[4];
#pragma unroll
        for (int i = 0; i < 4; ++i) {
            unsigned v = __float_as_uint(As[(r0 + i) * AS_LD + k]);
            asm("mov.b64 %0, {%1, %1};" : "=l"(h[i]) : "r"(v));
        }
        const float* wr = Ws + k * HID + c0;
        ulonglong2 wa = *(const ulonglong2*)(wr);
        ulonglong2 wb = *(const ulonglong2*)(wr + 4);
#pragma unroll
        for (int i = 0; i < 4; ++i) {
            asm("fma.rn.f32x2 %0, %1, %2, %0;" : "+l"(acc[i][0]) : "l"(h[i]), "l"(wa.x));
            asm("fma.rn.f32x2 %0, %1, %2, %0;" : "+l"(acc[i][1]) : "l"(h[i]), "l"(wa.y));
            asm("fma.rn.f32x2 %0, %1, %2, %0;" : "+l"(acc[i][2]) : "l"(h[i]), "l"(wb.x));
            asm("fma.rn.f32x2 %0, %1, %2, %0;" : "+l"(acc[i][3]) : "l"(h[i]), "l"(wb.y));
        }
    }
}

__global__ void __launch_bounds__(256, 2)
ctx_kernel(const float* __restrict__ X, const float* __restrict__ W1,
           const float* __restrict__ b1, int which) {
    extern __shared__ float sm[];
    float* Ws = sm;
    float* Xs = sm + HID * HID;
    float* out = which ? g_cctx : g_dctx;
    int tid = threadIdx.x;
    size_t row0 = (size_t)blockIdx.x * 64;
    for (int i = tid; i < HID * HID; i += 256) Ws[i] = W1[2 * HID + i];
#pragma unroll 4
    for (int i = tid; i < 64 * HID; i += 256) {
        int r = i >> 7, c = i & 127;
        Xs[r * AS_LD + c] = X[(row0 + r) * HID + c];
    }
    __syncthreads();
    int r0 = (tid >> 4) * 4, c0 = (tid & 15) * 8;
    unsigned long long acc[4][4];
    gemm_core(Xs, Ws, r0, c0, acc);
#pragma unroll
    for (int i = 0; i < 4; ++i) {
        size_t base = (row0 + r0 + i) * HID + c0;
#pragma unroll
        for (int j = 0; j < 4; ++j) {
            unsigned lo, hi;
            asm("mov.b64 {%0, %1}, %2;" : "=r"(lo), "=r"(hi) : "l"(acc[i][j]));
            float2 v;
            v.x = __uint_as_float(lo) + b1[c0 + 2 * j];
            v.y = __uint_as_float(hi) + b1[c0 + 2 * j + 1];
            *(float2*)&out[base + 2 * j] = v;
        }
    }
}

__global__ void __launch_bounds__(128)
step_const_kernel(const float* __restrict__ times, const float* __restrict__ freqs,
                  const float* __restrict__ dW1, const float* __restrict__ cW1,
                  const float* __restrict__ logd, float* __restrict__ out) {
    int s = blockIdx.x, t = threadIdx.x;
    __shared__ float temb[32];
    float t_i = times[s];
    if (t < 32) {
        float a = 6.28318530717958647692f * t_i * freqs[t & 15];
        temb[t] = (t < 16) ? sinf(a) : cosf(a);
    }
    __syncthreads();
    float sd = 0.0f, sc = 0.0f;
#pragma unroll
    for (int k = 0; k < 32; ++k) {
        sd += temb[k] * dW1[(130 + k) * HID + t];
        sc += temb[k] * cW1[(130 + k) * HID + t];
    }
    g_tvd[s * HID + t] = sd;
    g_tvc[s * HID + t] = sc;
    if (t == 0) {
        float dt = times[s + 1] - t_i;
        g_dt[s] = dt;
        g_gs[s] = log1pf(expf(logd[0])) * (1.0f - t_i) * sqrtf(fmaxf(dt, 1e-12f));
    }
    if (s == 0 && t < NSTEPS + 1) out[OUT_TIMES + t] = times[t];
}

// ---------- main HMMA SDE kernel ----------
// smem tile word offsets (each tile 128 rows x 136 bf16 = 8704 words)
#define T_AHI 0
#define T_ALO 8704
#define T_WDH 17408
#define T_WDL 26112
#define T_WCH 34816
#define T_WCL 43520
#define T_FLT 52224
#define SDE_WORDS (T_FLT + 2820)
#define SDE_SMEM (SDE_WORDS * 4)

// layer1: h = silu(preb + tv + z@W1z), split into bf16 hi/lo tiles
__device__ __forceinline__ void layer1(const float* __restrict__ preb,
                                       const float* __restrict__ tv,
                                       const float* __restrict__ w1z,
                                       const float* __restrict__ zsm,
                                       uint32_t* __restrict__ Ah,
                                       uint32_t* __restrict__ Al, int tid) {
#pragma unroll 4
    for (int p = tid; p < ROWS * 64; p += 256) {
        int r = p >> 6, c = (p & 63) * 2;
        float2 pv = *(const float2*)(preb + r * HID + c);
        float2 tw = *(const float2*)(tv + c);
        float2 wa = *(const float2*)(w1z + c);
        float2 wb = *(const float2*)(w1z + HID + c);
        float za = zsm[2 * r], zb = zsm[2 * r + 1];
        float h0 = siluf(pv.x + tw.x + za * wa.x + zb * wb.x);
        float h1 = siluf(pv.y + tw.y + za * wa.y + zb * wb.y);
        uint32_t hp;
        asm("cvt.rn.bf16x2.f32 %0,%1,%2;" : "=r"(hp) : "f"(h1), "f"(h0));
        float l0 = h0 - __uint_as_float(hp << 16);
        float l1 = h1 - __uint_as_float(hp & 0xFFFF0000u);
        uint32_t lp;
        asm("cvt.rn.bf16x2.f32 %0,%1,%2;" : "=r"(lp) : "f"(l1), "f"(l0));
        int w = r * LDAW + (c >> 1);
        Ah[w] = hp;
        Al[w] = lp;
    }
}

// one net: C = A@W (3-pass hi/lo HMMA), fused bias+silu+layer3 dot, stage partials
__device__ __forceinline__ void net_pass(const uint32_t* __restrict__ Ah,
                                         const uint32_t* __restrict__ Al,
                                         const uint32_t* __restrict__ Wh,
                                         const uint32_t* __restrict__ Wl,
                                         const float* __restrict__ b2,
                                         const float* __restrict__ w3,
                                         float* __restrict__ st0, float* __restrict__ st1,
                                         int wid, int lane) {
    int wm = wid & 3, wn = wid >> 2, g = lane >> 2, tg = lane & 3;
    float acc[2][8][4];
#pragma unroll
    for (int mt = 0; mt < 2; ++mt)
#pragma unroll
        for (int nt = 0; nt < 8; ++nt)
#pragma unroll
            for (int q = 0; q < 4; ++q) acc[mt][nt][q] = 0.0f;

#pragma unroll
    for (int kc = 0; kc < 8; ++kc) {
        int kw = kc * 8 + tg;
        uint32_t bh[8][2], bl[8][2], ah[2][4], al[2][4];
#pragma unroll
        for (int nt = 0; nt < 8; ++nt) {
            int nw = (wn * 64 + nt * 8 + g) * LDAW + kw;
            bh[nt][0] = Wh[nw]; bh[nt][1] = Wh[nw + 4];
            bl[nt][0] = Wl[nw]; bl[nt][1] = Wl[nw + 4];
        }
#pragma unroll
        for (int mt = 0; mt < 2; ++mt) {
            int rw = (wm * 32 + mt * 16 + g) * LDAW + kw;
            ah[mt][0] = Ah[rw];            ah[mt][1] = Ah[rw + 8 * LDAW];
            ah[mt][2] = Ah[rw + 4];        ah[mt][3] = Ah[rw + 8 * LDAW + 4];
            al[mt][0] = Al[rw];            al[mt][1] = Al[rw + 8 * LDAW];
            al[mt][2] = Al[rw + 4];        al[mt][3] = Al[rw + 8 * LDAW + 4];
        }
#pragma unroll
        for (int mt = 0; mt < 2; ++mt)
#pragma unroll
            for (int nt = 0; nt < 8; ++nt) {
                MMA(acc[mt][nt], ah[mt], bh[nt]);
                MMA(acc[mt][nt], ah[mt], bl[nt]);
                MMA(acc[mt][nt], al[mt], bh[nt]);
            }
    }

    // epilogue: silu + partial layer3 dot (this warp covers 64 of 128 cols)
    float p0[4] = {0, 0, 0, 0}, p1[4] = {0, 0, 0, 0};
#pragma unroll
    for (int nt = 0; nt < 8; ++nt) {
        int c0 = wn * 64 + nt * 8 + tg * 2;
        float bA = b2[c0], bB = b2[c0 + 1];
        float2 wA = *(const float2*)(w3 + c0 * 2);
        float2 wB = *(const float2*)(w3 + c0 * 2 + 2);
#pragma unroll
        for (int mt = 0; mt < 2; ++mt)
#pragma unroll
            for (int hf = 0; hf < 2; ++hf) {
                float h0 = siluf(acc[mt][nt][hf * 2] + bA);
                float h1 = siluf(acc[mt][nt][hf * 2 + 1] + bB);
                int i = mt * 2 + hf;
                p0[i] += h0 * wA.x + h1 * wB.x;
                p1[i] += h0 * wA.y + h1 * wB.y;
            }
    }
#pragma unroll
    for (int i = 0; i < 4; ++i) {
        p0[i] += __shfl_xor_sync(~0u, p0[i], 1);
        p0[i] += __shfl_xor_sync(~0u, p0[i], 2);
        p1[i] += __shfl_xor_sync(~0u, p1[i], 1);
        p1[i] += __shfl_xor_sync(~0u, p1[i], 2);
    }
    if (tg == 0) {
        float* st = wn ? st1 : st0;
#pragma unroll
        for (int i = 0; i < 4; ++i) {
            int row = wm * 32 + (i >> 1) * 16 + g + (i & 1) * 8;
            st[row * 2]     = p0[i];
            st[row * 2 + 1] = p1[i];
        }
    }
}

__global__ void __launch_bounds__(256, 1)
sde_mma_kernel(const float* __restrict__ z0, const float* __restrict__ noise,
               const float* __restrict__ dW1, const float* __restrict__ dW2,
               const float* __restrict__ db2, const float* __restrict__ dW3,
               const float* __restrict__ db3,
               const float* __restrict__ cW1, const float* __restrict__ cW2,
               const float* __restrict__ cb2, const float* __restrict__ cW3,
               const float* __restrict__ cb3, float* __restrict__ out) {
    extern __shared__ uint32_t sw[];
    float* fs   = (float*)(sw + T_FLT);
    float* zsm  = fs;            // 256
    float* tvd  = fs + 256;      // 128
    float* tvc  = fs + 384;      // 128
    float* w1zd = fs + 512;      // 256
    float* w1zc = fs + 768;      // 256
    float* b2d  = fs + 1024;     // 128
    float* b2c  = fs + 1152;     // 128
    float* w3d  = fs + 1280;     // 256
    float* w3c  = fs + 1536;     // 256
    float* su0  = fs + 1792;     // 256
    float* su1  = fs + 2048;     // 256
    float* sf0  = fs + 2304;     // 256
    float* sf1  = fs + 2560;     // 256
    float* b3s  = fs + 2816;     // 4

    int tid = threadIdx.x, wid = tid >> 5, lane = tid & 31;
    size_t row0 = (size_t)blockIdx.x * ROWS;

    // W2 transposed (Wt[n][k]) + bf16 hi/lo split, both nets
    for (int i = tid; i < HID * HID; i += 256) {
        int k = i >> 7, n = i & 127;
        float wd = dW2[i], wc = cW2[i];
        __nv_bfloat16 h;
        h = __float2bfloat16(wd);
        ((__nv_bfloat16*)(sw + T_WDH))[n * 136 + k] = h;
        ((__nv_bfloat16*)(sw + T_WDL))[n * 136 + k] = __float2bfloat16(wd - __bfloat162float(h));
        h = __float2bfloat16(wc);
        ((__nv_bfloat16*)(sw + T_WCH))[n * 136 + k] = h;
        ((__nv_bfloat16*)(sw + T_WCL))[n * 136 + k] = __float2bfloat16(wc - __bfloat162float(h));
    }
    w1zd[tid] = dW1[tid]; w1zc[tid] = cW1[tid];
    w3d[tid] = dW3[tid];  w3c[tid] = cW3[tid];
    if (tid < 128) { b2d[tid] = db2[tid]; b2c[tid] = cb2[tid]; }
    if (tid < 2)   { b3s[tid] = db3[tid]; b3s[2 + tid] = cb3[tid]; }
    {
        float zv = z0[row0 * 2 + tid];
        zsm[tid] = zv;
        out[row0 * 2 + tid] = zv;   // traj[0]
    }
    __syncthreads();

    for (int s = 0; s < NSTEPS; ++s) {
        if (tid < 128) tvd[tid] = g_tvd[s * HID + tid];
        else           tvc[tid - 128] = g_tvc[s * HID + tid - 128];
        float dt = g_dt[s], gsc = g_gs[s];
        float xi = noise[(size_t)s * ((size_t)NPTS * 2) + row0 * 2 + tid];  // prefetch
        __syncthreads();

        layer1(g_dctx + row0 * HID, tvd, w1zd, zsm, sw + T_AHI, sw + T_ALO, tid);
        __syncthreads();
        net_pass(sw + T_AHI, sw + T_ALO, sw + T_WDH, sw + T_WDL, b2d, w3d, su0, su1, wid, lane);
        __syncthreads();

        layer1(g_cctx + row0 * HID, tvc, w1zc, zsm, sw + T_AHI, sw + T_ALO, tid);
        __syncthreads();
        net_pass(sw + T_AHI, sw + T_ALO, sw + T_WCH, sw + T_WCL, b2c, w3c, sf0, sf1, wid, lane);
        __syncthreads();

        {   // SDE update: 256 threads = 128 rows x 2 dims
            float au = su0[tid] + su1[tid] + b3s[tid & 1];
            float af = sf0[tid] + sf1[tid] + b3s[2 + (tid & 1)];
            size_t gi = row0 * 2 + tid;
            float zn = zsm[tid] + (af + au) * dt + xi * gsc;
            out[OUT_US + (size_t)s * ((size_t)NPTS * 2) + gi] = au;
            out[(size_t)(s + 1) * ((size_t)NPTS * 2) + gi]    = zn;
            zsm[tid] = zn;
        }
        __syncthreads();
    }
}

extern "C" void kernel_launch(void* const* d_in, const int* in_sizes, int n_in,
                              void* d_out, int out_size) {
    (void)in_sizes; (void)n_in; (void)out_size;
    const float* z0    = (const float*)d_in[0];
    const float* pctx  = (const float*)d_in[1];
    const float* cctx  = (const float*)d_in[2];
    const float* times = (const float*)d_in[3];
    const float* noise = (const float*)d_in[4];
    const float* freqs = (const float*)d_in[5];
    const float* dW1   = (const float*)d_in[6];
    const float* db1   = (const float*)d_in[7];
    const float* dW2   = (const float*)d_in[8];
    const float* db2   = (const float*)d_in[9];
    const float* dW3   = (const float*)d_in[10];
    const float* db3   = (const float*)d_in[11];
    const float* cW1   = (const float*)d_in[12];
    const float* cb1   = (const float*)d_in[13];
    const float* cW2   = (const float*)d_in[14];
    const float* cb2   = (const float*)d_in[15];
    const float* cW3   = (const float*)d_in[16];
    const float* cb3   = (const float*)d_in[17];
    const float* logd  = (const float*)d_in[18];
    float* out = (float*)d_out;

    const int CTX_SMEM = (HID * HID + 64 * AS_LD) * (int)sizeof(float);
    static int done = 0;
    if (!done) {
        cudaFuncSetAttribute(ctx_kernel, cudaFuncAttributeMaxDynamicSharedMemorySize, CTX_SMEM);
        cudaFuncSetAttribute(sde_mma_kernel, cudaFuncAttributeMaxDynamicSharedMemorySize, SDE_SMEM);
        done = 1;
    }
    step_const_kernel<<<NSTEPS, 128>>>(times, freqs, dW1, cW1, logd, out);
    ctx_kernel<<<NPTS / 64, 256, CTX_SMEM>>>(pctx, dW1, db1, 0);
    ctx_kernel<<<NPTS / 64, 256, CTX_SMEM>>>(cctx, cW1, cb1, 1);
    sde_mma_kernel<<<NPTS / ROWS, 256, SDE_SMEM>>>(z0, noise, dW1, dW2, db2, dW3, db3,
                                                   cW1, cW2, cb2, cW3, cb3, out);
}

// round 10
// speedup vs baseline: 4.7987x; 1.5407x over previous
#include <cuda_runtime.h>
#include <cuda_bf16.h>
#include <cuda_fp16.h>
#include <math.h>
#include <stdint.h>

#define NPTS 262144
#define HID 128
#define NSTEPS 50
#define AS_LD 129
#define ROWS 128
#define LDAW 68   // uint32 words per tile row (136 halves) -> conflict-free frags

#define OUT_US    ((size_t)(NSTEPS + 1) * NPTS * 2)
#define OUT_TIMES (OUT_US + (size_t)NSTEPS * NPTS * 2)

__device__ float g_dctx[NPTS * HID];
__device__ float g_cctx[NPTS * HID];
__device__ float g_tvd[NSTEPS * HID];
__device__ float g_tvc[NSTEPS * HID];
__device__ float g_dt[NSTEPS];
__device__ float g_gs[NSTEPS];

__device__ __forceinline__ float siluf(float x) {
    return __fdividef(x, 1.0f + __expf(-x));
}

#define MMAH(d, a, b0, b1) asm volatile( \
    "mma.sync.aligned.m16n8k16.row.col.f32.f16.f16.f32 " \
    "{%0,%1,%2,%3},{%4,%5,%6,%7},{%8,%9},{%0,%1,%2,%3};" \
    : "+f"((d)[0]), "+f"((d)[1]), "+f"((d)[2]), "+f"((d)[3]) \
    : "r"((a)[0]), "r"((a)[1]), "r"((a)[2]), "r"((a)[3]), "r"(b0), "r"(b1))

// ---------- FFMA2 GEMM (ctx precompute, known-good) ----------
__device__ __forceinline__ void gemm_core(const float* __restrict__ As,
                                          const float* __restrict__ Ws,
                                          int r0, int c0, unsigned long long (&acc)[4][4]) {
#pragma unroll
    for (int i = 0; i < 4; ++i)
#pragma unroll
        for (int j = 0; j < 4; ++j) acc[i][j] = 0ull;
#pragma unroll 4
    for (int k = 0; k < HID; ++k) {
        unsigned long long h[4];
#pragma unroll
        for (int i = 0; i < 4; ++i) {
            unsigned v = __float_as_uint(As[(r0 + i) * AS_LD + k]);
            asm("mov.b64 %0, {%1, %1};" : "=l"(h[i]) : "r"(v));
        }
        const float* wr = Ws + k * HID + c0;
        ulonglong2 wa = *(const ulonglong2*)(wr);
        ulonglong2 wb = *(const ulonglong2*)(wr + 4);
#pragma unroll
        for (int i = 0; i < 4; ++i) {
            asm("fma.rn.f32x2 %0, %1, %2, %0;" : "+l"(acc[i][0]) : "l"(h[i]), "l"(wa.x));
            asm("fma.rn.f32x2 %0, %1, %2, %0;" : "+l"(acc[i][1]) : "l"(h[i]), "l"(wa.y));
            asm("fma.rn.f32x2 %0, %1, %2, %0;" : "+l"(acc[i][2]) : "l"(h[i]), "l"(wb.x));
            asm("fma.rn.f32x2 %0, %1, %2, %0;" : "+l"(acc[i][3]) : "l"(h[i]), "l"(wb.y));
        }
    }
}

__global__ void __launch_bounds__(256, 2)
ctx_kernel(const float* __restrict__ X, const float* __restrict__ W1,
           const float* __restrict__ b1, int which) {
    extern __shared__ float sm[];
    float* Ws = sm;
    float* Xs = sm + HID * HID;
    float* out = which ? g_cctx : g_dctx;
    int tid = threadIdx.x;
    size_t row0 = (size_t)blockIdx.x * 64;
    for (int i = tid; i < HID * HID; i += 256) Ws[i] = W1[2 * HID + i];
#pragma unroll 4
    for (int i = tid; i < 64 * HID; i += 256) {
        int r = i >> 7, c = i & 127;
        Xs[r * AS_LD + c] = X[(row0 + r) * HID + c];
    }
    __syncthreads();
    int r0 = (tid >> 4) * 4, c0 = (tid & 15) * 8;
    unsigned long long acc[4][4];
    gemm_core(Xs, Ws, r0, c0, acc);
#pragma unroll
    for (int i = 0; i < 4; ++i) {
        size_t base = (row0 + r0 + i) * HID + c0;
#pragma unroll
        for (int j = 0; j < 4; ++j) {
            unsigned lo, hi;
            asm("mov.b64 {%0, %1}, %2;" : "=r"(lo), "=r"(hi) : "l"(acc[i][j]));
            float2 v;
            v.x = __uint_as_float(lo) + b1[c0 + 2 * j];
            v.y = __uint_as_float(hi) + b1[c0 + 2 * j + 1];
            *(float2*)&out[base + 2 * j] = v;
        }
    }
}

__global__ void __launch_bounds__(128)
step_const_kernel(const float* __restrict__ times, const float* __restrict__ freqs,
                  const float* __restrict__ dW1, const float* __restrict__ cW1,
                  const float* __restrict__ logd, float* __restrict__ out) {
    int s = blockIdx.x, t = threadIdx.x;
    __shared__ float temb[32];
    float t_i = times[s];
    if (t < 32) {
        float a = 6.28318530717958647692f * t_i * freqs[t & 15];
        temb[t] = (t < 16) ? sinf(a) : cosf(a);
    }
    __syncthreads();
    float sd = 0.0f, sc = 0.0f;
#pragma unroll
    for (int k = 0; k < 32; ++k) {
        sd += temb[k] * dW1[(130 + k) * HID + t];
        sc += temb[k] * cW1[(130 + k) * HID + t];
    }
    g_tvd[s * HID + t] = sd;
    g_tvc[s * HID + t] = sc;
    if (t == 0) {
        float dt = times[s + 1] - t_i;
        g_dt[s] = dt;
        g_gs[s] = log1pf(expf(logd[0])) * (1.0f - t_i) * sqrtf(fmaxf(dt, 1e-12f));
    }
    if (s == 0 && t < NSTEPS + 1) out[OUT_TIMES + t] = times[t];
}

// ---------- main HMMA SDE kernel: 512 threads, net-parallel halves ----------
// word offsets; each tile 128 x 68 uint32 = 8704 words
#define T_AD  0
#define T_AC  8704
#define T_WDH 17408
#define T_WDL 26112
#define T_WCH 34816
#define T_WCL 43520
#define T_FLT 52224
#define SDE_WORDS (T_FLT + 2052)
#define SDE_SMEM (SDE_WORDS * 4)

// GEMM + fused epilogue for one net; 8 warps (widh 0..7), tile 32r x 64c per warp
__device__ __forceinline__ void net_pass(const uint32_t* __restrict__ At,
                                         const uint32_t* __restrict__ Wh,
                                         const uint32_t* __restrict__ Wl,
                                         const float* __restrict__ b2,
                                         const float* __restrict__ w3,
                                         float* __restrict__ st0, float* __restrict__ st1,
                                         int widh, int lane) {
    int wm = widh & 3, wn = widh >> 2, g = lane >> 2, tg = lane & 3;
    float acc[2][8][4];
#pragma unroll
    for (int mt = 0; mt < 2; ++mt)
#pragma unroll
        for (int nt = 0; nt < 8; ++nt)
#pragma unroll
            for (int q = 0; q < 4; ++q) acc[mt][nt][q] = 0.0f;

#pragma unroll
    for (int kc = 0; kc < 8; ++kc) {
        int kw = kc * 8 + tg;
        uint32_t ah[2][4];
#pragma unroll
        for (int mt = 0; mt < 2; ++mt) {
            int rw = (wm * 32 + mt * 16 + g) * LDAW + kw;
            ah[mt][0] = At[rw];     ah[mt][1] = At[rw + 8 * LDAW];
            ah[mt][2] = At[rw + 4]; ah[mt][3] = At[rw + 8 * LDAW + 4];
        }
#pragma unroll
        for (int nt = 0; nt < 8; ++nt) {
            int nw = (wn * 64 + nt * 8 + g) * LDAW + kw;
            uint32_t bh0 = Wh[nw], bh1 = Wh[nw + 4];
            uint32_t bl0 = Wl[nw], bl1 = Wl[nw + 4];
            MMAH(acc[0][nt], ah[0], bh0, bh1);
            MMAH(acc[0][nt], ah[0], bl0, bl1);
            MMAH(acc[1][nt], ah[1], bh0, bh1);
            MMAH(acc[1][nt], ah[1], bl0, bl1);
        }
    }

    // epilogue: bias + silu + partial layer3 dot (this warp covers 64 cols)
    float p0[4] = {0, 0, 0, 0}, p1[4] = {0, 0, 0, 0};
#pragma unroll
    for (int nt = 0; nt < 8; ++nt) {
        int c0 = wn * 64 + nt * 8 + tg * 2;
        float bA = b2[c0], bB = b2[c0 + 1];
        float2 wA = *(const float2*)(w3 + c0 * 2);
        float2 wB = *(const float2*)(w3 + c0 * 2 + 2);
#pragma unroll
        for (int mt = 0; mt < 2; ++mt)
#pragma unroll
            for (int hf = 0; hf < 2; ++hf) {
                float h0 = siluf(acc[mt][nt][hf * 2] + bA);
                float h1 = siluf(acc[mt][nt][hf * 2 + 1] + bB);
                int i = mt * 2 + hf;
                p0[i] += h0 * wA.x + h1 * wB.x;
                p1[i] += h0 * wA.y + h1 * wB.y;
            }
    }
#pragma unroll
    for (int i = 0; i < 4; ++i) {
        p0[i] += __shfl_xor_sync(~0u, p0[i], 1);
        p0[i] += __shfl_xor_sync(~0u, p0[i], 2);
        p1[i] += __shfl_xor_sync(~0u, p1[i], 1);
        p1[i] += __shfl_xor_sync(~0u, p1[i], 2);
    }
    if (tg == 0) {
        float* st = wn ? st1 : st0;
#pragma unroll
        for (int i = 0; i < 4; ++i) {
            int row = wm * 32 + (i >> 1) * 16 + g + (i & 1) * 8;
            st[row * 2]     = p0[i];
            st[row * 2 + 1] = p1[i];
        }
    }
}

__global__ void __launch_bounds__(512, 1)
sde_mma_kernel(const float* __restrict__ z0, const float* __restrict__ noise,
               const float* __restrict__ dW1, const float* __restrict__ dW2,
               const float* __restrict__ db2, const float* __restrict__ dW3,
               const float* __restrict__ db3,
               const float* __restrict__ cW1, const float* __restrict__ cW2,
               const float* __restrict__ cb2, const float* __restrict__ cW3,
               const float* __restrict__ cb3, float* __restrict__ out) {
    extern __shared__ uint32_t sw[];
    float* fs   = (float*)(sw + T_FLT);
    float* zsm  = fs;            // 256
    float* b2d  = fs + 256;      // 128
    float* b2c  = fs + 384;      // 128
    float* w3d  = fs + 512;      // 256
    float* w3c  = fs + 768;      // 256
    float* su0  = fs + 1024;     // 256
    float* su1  = fs + 1280;     // 256
    float* sf0  = fs + 1536;     // 256
    float* sf1  = fs + 1792;     // 256
    float* b3s  = fs + 2048;     // 4

    int tid = threadIdx.x, lane = tid & 31;
    int h = tid >> 8;            // half: 0=diffusion, 1=cnf
    int htid = tid & 255;
    int widh = htid >> 5;        // warp within half
    size_t row0 = (size_t)blockIdx.x * ROWS;

    // W2 transposed (Wt[n][k]) + fp16 hi/lo split, both nets
    for (int i = tid; i < HID * HID; i += 512) {
        int k = i >> 7, n = i & 127;
        float wd = dW2[i], wc = cW2[i];
        __half hh;
        hh = __float2half(wd);
        ((__half*)(sw + T_WDH))[n * 136 + k] = hh;
        ((__half*)(sw + T_WDL))[n * 136 + k] = __float2half(wd - __half2float(hh));
        hh = __float2half(wc);
        ((__half*)(sw + T_WCH))[n * 136 + k] = hh;
        ((__half*)(sw + T_WCL))[n * 136 + k] = __float2half(wc - __half2float(hh));
    }
    if (tid < 128)      b2d[tid] = db2[tid];
    else if (tid < 256) b2c[tid - 128] = cb2[tid - 128];
    if (tid < 256) w3d[tid] = dW3[tid];
    else           w3c[tid - 256] = cW3[tid - 256];
    if (tid < 2)   { b3s[tid] = db3[tid]; b3s[2 + tid] = cb3[tid]; }
    if (tid < 256) {
        float zv = z0[row0 * 2 + tid];
        zsm[tid] = zv;
        out[row0 * 2 + tid] = zv;   // traj[0]
    }

    // per-thread layer1 constants (column is fixed per thread)
    int cc = (htid & 63) * 2;
    const float* W1g = h ? cW1 : dW1;
    float w1aa = W1g[cc], w1ab = W1g[cc + 1];
    float w1ba = W1g[HID + cc], w1bb = W1g[HID + cc + 1];
    const float* prebase = (h ? g_cctx : g_dctx) + row0 * HID + cc;
    const float* tvg = h ? g_tvc : g_tvd;
    uint32_t* At = sw + (h ? T_AC : T_AD);
    const uint32_t* Wth = sw + (h ? T_WCH : T_WDH);
    const uint32_t* Wtl = sw + (h ? T_WCL : T_WDL);
    const float* b2 = h ? b2c : b2d;
    const float* w3 = h ? w3c : w3d;
    float* st0 = h ? sf0 : su0;
    float* st1 = h ? sf1 : su1;
    int aw = (cc >> 1);
    __syncthreads();

    for (int s = 0; s < NSTEPS; ++s) {
        float2 tvv = *(const float2*)(tvg + s * HID + cc);
        float dt = g_dt[s], gsc = g_gs[s];
        float xi = 0.0f;
        if (tid < 256) xi = noise[(size_t)s * ((size_t)NPTS * 2) + row0 * 2 + tid];

        // layer1 for this half's net -> fp16 A tile
        {
            int r = htid >> 6;
#pragma unroll 4
            for (int k = 0; k < 32; ++k, r += 4) {
                float2 pv = *(const float2*)(prebase + r * HID);
                float za = zsm[2 * r], zb = zsm[2 * r + 1];
                float h0 = siluf(pv.x + tvv.x + za * w1aa + zb * w1ba);
                float h1 = siluf(pv.y + tvv.y + za * w1ab + zb * w1bb);
                uint32_t pk;
                asm("cvt.rn.f16x2.f32 %0,%1,%2;" : "=r"(pk) : "f"(h1), "f"(h0));
                At[r * LDAW + aw] = pk;
            }
        }
        asm volatile("bar.sync %0, 256;" :: "r"(1 + h) : "memory");

        net_pass(At, Wth, Wtl, b2, w3, st0, st1, widh, lane);
        __syncthreads();

        if (tid < 256) {   // SDE update: 256 threads = 128 rows x 2 dims
            float au = su0[tid] + su1[tid] + b3s[tid & 1];
            float af = sf0[tid] + sf1[tid] + b3s[2 + (tid & 1)];
            size_t gi = row0 * 2 + tid;
            float zn = zsm[tid] + (af + au) * dt + xi * gsc;
            out[OUT_US + (size_t)s * ((size_t)NPTS * 2) + gi] = au;
            out[(size_t)(s + 1) * ((size_t)NPTS * 2) + gi]    = zn;
            zsm[tid] = zn;
        }
        __syncthreads();   // zsm visible, stages free for next step
    }
}

extern "C" void kernel_launch(void* const* d_in, const int* in_sizes, int n_in,
                              void* d_out, int out_size) {
    (void)in_sizes; (void)n_in; (void)out_size;
    const float* z0    = (const float*)d_in[0];
    const float* pctx  = (const float*)d_in[1];
    const float* cctx  = (const float*)d_in[2];
    const float* times = (const float*)d_in[3];
    const float* noise = (const float*)d_in[4];
    const float* freqs = (const float*)d_in[5];
    const float* dW1   = (const float*)d_in[6];
    const float* db1   = (const float*)d_in[7];
    const float* dW2   = (const float*)d_in[8];
    const float* db2   = (const float*)d_in[9];
    const float* dW3   = (const float*)d_in[10];
    const float* db3   = (const float*)d_in[11];
    const float* cW1   = (const float*)d_in[12];
    const float* cb1   = (const float*)d_in[13];
    const float* cW2   = (const float*)d_in[14];
    const float* cb2   = (const float*)d_in[15];
    const float* cW3   = (const float*)d_in[16];
    const float* cb3   = (const float*)d_in[17];
    const float* logd  = (const float*)d_in[18];
    float* out = (float*)d_out;

    const int CTX_SMEM = (HID * HID + 64 * AS_LD) * (int)sizeof(float);
    static int done = 0;
    if (!done) {
        cudaFuncSetAttribute(ctx_kernel, cudaFuncAttributeMaxDynamicSharedMemorySize, CTX_SMEM);
        cudaFuncSetAttribute(sde_mma_kernel, cudaFuncAttributeMaxDynamicSharedMemorySize, SDE_SMEM);
        done = 1;
    }
    step_const_kernel<<<NSTEPS, 128>>>(times, freqs, dW1, cW1, logd, out);
    ctx_kernel<<<NPTS / 64, 256, CTX_SMEM>>>(pctx, dW1, db1, 0);
    ctx_kernel<<<NPTS / 64, 256, CTX_SMEM>>>(cctx, cW1, cb1, 1);
    sde_mma_kernel<<<NPTS / ROWS, 512, SDE_SMEM>>>(z0, noise, dW1, dW2, db2, dW3, db3,
                                                   cW1, cW2, cb2, cW3, cb3, out);
}

// round 11
// speedup vs baseline: 6.9573x; 1.4498x over previous
#include <cuda_runtime.h>
#include <cuda_bf16.h>
#include <cuda_fp16.h>
#include <math.h>
#include <stdint.h>

#define NPTS 262144
#define HID 128
#define NSTEPS 50
#define AS_LD 129
#define ROWS 128
#define LDAW 68   // uint32 words per tile row (136 halves) -> conflict-free frags

#define OUT_US    ((size_t)(NSTEPS + 1) * NPTS * 2)
#define OUT_TIMES (OUT_US + (size_t)NSTEPS * NPTS * 2)

__device__ float g_dctx[NPTS * HID];
__device__ float g_cctx[NPTS * HID];
__device__ float g_tvd[NSTEPS * HID];
__device__ float g_tvc[NSTEPS * HID];
__device__ float g_dt[NSTEPS];
__device__ float g_gs[NSTEPS];

// exact silu for precompute path (not used in hot loop)
__device__ __forceinline__ float siluf_exact(float x) {
    return __fdividef(x, 1.0f + __expf(-x));
}
// fast silu: 1 MUFU (tanh.approx) + 2 FMA
__device__ __forceinline__ float siluf(float x) {
    float t;
    asm("tanh.approx.f32 %0, %1;" : "=f"(t) : "f"(x * 0.5f));
    return x * fmaf(0.5f, t, 0.5f);
}

#define MMAH(d, a, b0, b1) asm volatile( \
    "mma.sync.aligned.m16n8k16.row.col.f32.f16.f16.f32 " \
    "{%0,%1,%2,%3},{%4,%5,%6,%7},{%8,%9},{%0,%1,%2,%3};" \
    : "+f"((d)[0]), "+f"((d)[1]), "+f"((d)[2]), "+f"((d)[3]) \
    : "r"((a)[0]), "r"((a)[1]), "r"((a)[2]), "r"((a)[3]), "r"(b0), "r"(b1))

// ---------- FFMA2 GEMM (ctx precompute, known-good) ----------
__device__ __forceinline__ void gemm_core(const float* __restrict__ As,
                                          const float* __restrict__ Ws,
                                          int r0, int c0, unsigned long long (&acc)[4][4]) {
#pragma unroll
    for (int i = 0; i < 4; ++i)
#pragma unroll
        for (int j = 0; j < 4; ++j) acc[i][j] = 0ull;
#pragma unroll 4
    for (int k = 0; k < HID; ++k) {
        unsigned long long h[4];
#pragma unroll
        for (int i = 0; i < 4; ++i) {
            unsigned v = __float_as_uint(As[(r0 + i) * AS_LD + k]);
            asm("mov.b64 %0, {%1, %1};" : "=l"(h[i]) : "r"(v));
        }
        const float* wr = Ws + k * HID + c0;
        ulonglong2 wa = *(const ulonglong2*)(wr);
        ulonglong2 wb = *(const ulonglong2*)(wr + 4);
#pragma unroll
        for (int i = 0; i < 4; ++i) {
            asm("fma.rn.f32x2 %0, %1, %2, %0;" : "+l"(acc[i][0]) : "l"(h[i]), "l"(wa.x));
            asm("fma.rn.f32x2 %0, %1, %2, %0;" : "+l"(acc[i][1]) : "l"(h[i]), "l"(wa.y));
            asm("fma.rn.f32x2 %0, %1, %2, %0;" : "+l"(acc[i][2]) : "l"(h[i]), "l"(wb.x));
            asm("fma.rn.f32x2 %0, %1, %2, %0;" : "+l"(acc[i][3]) : "l"(h[i]), "l"(wb.y));
        }
    }
}

__global__ void __launch_bounds__(256, 2)
ctx_kernel(const float* __restrict__ X, const float* __restrict__ W1,
           const float* __restrict__ b1, int which) {
    extern __shared__ float sm[];
    float* Ws = sm;
    float* Xs = sm + HID * HID;
    float* out = which ? g_cctx : g_dctx;
    int tid = threadIdx.x;
    size_t row0 = (size_t)blockIdx.x * 64;
    for (int i = tid; i < HID * HID; i += 256) Ws[i] = W1[2 * HID + i];
#pragma unroll 4
    for (int i = tid; i < 64 * HID; i += 256) {
        int r = i >> 7, c = i & 127;
        Xs[r * AS_LD + c] = X[(row0 + r) * HID + c];
    }
    __syncthreads();
    int r0 = (tid >> 4) * 4, c0 = (tid & 15) * 8;
    unsigned long long acc[4][4];
    gemm_core(Xs, Ws, r0, c0, acc);
#pragma unroll
    for (int i = 0; i < 4; ++i) {
        size_t base = (row0 + r0 + i) * HID + c0;
#pragma unroll
        for (int j = 0; j < 4; ++j) {
            unsigned lo, hi;
            asm("mov.b64 {%0, %1}, %2;" : "=r"(lo), "=r"(hi) : "l"(acc[i][j]));
            float2 v;
            v.x = __uint_as_float(lo) + b1[c0 + 2 * j];
            v.y = __uint_as_float(hi) + b1[c0 + 2 * j + 1];
            *(float2*)&out[base + 2 * j] = v;
        }
    }
}

__global__ void __launch_bounds__(128)
step_const_kernel(const float* __restrict__ times, const float* __restrict__ freqs,
                  const float* __restrict__ dW1, const float* __restrict__ cW1,
                  const float* __restrict__ logd, float* __restrict__ out) {
    int s = blockIdx.x, t = threadIdx.x;
    __shared__ float temb[32];
    float t_i = times[s];
    if (t < 32) {
        float a = 6.28318530717958647692f * t_i * freqs[t & 15];
        temb[t] = (t < 16) ? sinf(a) : cosf(a);
    }
    __syncthreads();
    float sd = 0.0f, sc = 0.0f;
#pragma unroll
    for (int k = 0; k < 32; ++k) {
        sd += temb[k] * dW1[(130 + k) * HID + t];
        sc += temb[k] * cW1[(130 + k) * HID + t];
    }
    g_tvd[s * HID + t] = sd;
    g_tvc[s * HID + t] = sc;
    if (t == 0) {
        float dt = times[s + 1] - t_i;
        g_dt[s] = dt;
        g_gs[s] = log1pf(expf(logd[0])) * (1.0f - t_i) * sqrtf(fmaxf(dt, 1e-12f));
    }
    if (s == 0 && t < NSTEPS + 1) out[OUT_TIMES + t] = times[t];
}

// ---------- main HMMA SDE kernel: 512 threads, net-parallel halves ----------
// word offsets; each tile 128 x 68 uint32 = 8704 words
#define T_AD  0
#define T_AC  8704
#define T_WDH 17408
#define T_WCH 26112
#define T_FLT 34816
#define SDE_WORDS (T_FLT + 2052)
#define SDE_SMEM (SDE_WORDS * 4)

// GEMM + fused epilogue for one net; 8 warps (widh 0..7), tile 32r x 64c per warp
__device__ __forceinline__ void net_pass(const uint32_t* __restrict__ At,
                                         const uint32_t* __restrict__ Wh,
                                         const float* __restrict__ b2,
                                         const float* __restrict__ w3,
                                         float* __restrict__ st0, float* __restrict__ st1,
                                         int widh, int lane) {
    int wm = widh & 3, wn = widh >> 2, g = lane >> 2, tg = lane & 3;
    float acc[2][8][4];
#pragma unroll
    for (int mt = 0; mt < 2; ++mt)
#pragma unroll
        for (int nt = 0; nt < 8; ++nt)
#pragma unroll
            for (int q = 0; q < 4; ++q) acc[mt][nt][q] = 0.0f;

#pragma unroll
    for (int kc = 0; kc < 8; ++kc) {
        int kw = kc * 8 + tg;
        uint32_t ah[2][4];
#pragma unroll
        for (int mt = 0; mt < 2; ++mt) {
            int rw = (wm * 32 + mt * 16 + g) * LDAW + kw;
            ah[mt][0] = At[rw];     ah[mt][1] = At[rw + 8 * LDAW];
            ah[mt][2] = At[rw + 4]; ah[mt][3] = At[rw + 8 * LDAW + 4];
        }
#pragma unroll
        for (int nt = 0; nt < 8; ++nt) {
            int nw = (wn * 64 + nt * 8 + g) * LDAW + kw;
            uint32_t bh0 = Wh[nw], bh1 = Wh[nw + 4];
            MMAH(acc[0][nt], ah[0], bh0, bh1);
            MMAH(acc[1][nt], ah[1], bh0, bh1);
        }
    }

    // epilogue: bias + silu + partial layer3 dot (this warp covers 64 cols)
    float p0[4] = {0, 0, 0, 0}, p1[4] = {0, 0, 0, 0};
#pragma unroll
    for (int nt = 0; nt < 8; ++nt) {
        int c0 = wn * 64 + nt * 8 + tg * 2;
        float bA = b2[c0], bB = b2[c0 + 1];
        float2 wA = *(const float2*)(w3 + c0 * 2);
        float2 wB = *(const float2*)(w3 + c0 * 2 + 2);
#pragma unroll
        for (int mt = 0; mt < 2; ++mt)
#pragma unroll
            for (int hf = 0; hf < 2; ++hf) {
                float h0 = siluf(acc[mt][nt][hf * 2] + bA);
                float h1 = siluf(acc[mt][nt][hf * 2 + 1] + bB);
                int i = mt * 2 + hf;
                p0[i] += h0 * wA.x + h1 * wB.x;
                p1[i] += h0 * wA.y + h1 * wB.y;
            }
    }
#pragma unroll
    for (int i = 0; i < 4; ++i) {
        p0[i] += __shfl_xor_sync(~0u, p0[i], 1);
        p0[i] += __shfl_xor_sync(~0u, p0[i], 2);
        p1[i] += __shfl_xor_sync(~0u, p1[i], 1);
        p1[i] += __shfl_xor_sync(~0u, p1[i], 2);
    }
    if (tg == 0) {
        float* st = wn ? st1 : st0;
#pragma unroll
        for (int i = 0; i < 4; ++i) {
            int row = wm * 32 + (i >> 1) * 16 + g + (i & 1) * 8;
            st[row * 2]     = p0[i];
            st[row * 2 + 1] = p1[i];
        }
    }
}

__global__ void __launch_bounds__(512, 1)
sde_mma_kernel(const float* __restrict__ z0, const float* __restrict__ noise,
               const float* __restrict__ dW1, const float* __restrict__ dW2,
               const float* __restrict__ db2, const float* __restrict__ dW3,
               const float* __restrict__ db3,
               const float* __restrict__ cW1, const float* __restrict__ cW2,
               const float* __restrict__ cb2, const float* __restrict__ cW3,
               const float* __restrict__ cb3, float* __restrict__ out) {
    extern __shared__ uint32_t sw[];
    float* fs   = (float*)(sw + T_FLT);
    float* zsm  = fs;            // 256
    float* b2d  = fs + 256;      // 128
    float* b2c  = fs + 384;      // 128
    float* w3d  = fs + 512;      // 256
    float* w3c  = fs + 768;      // 256
    float* su0  = fs + 1024;     // 256
    float* su1  = fs + 1280;     // 256
    float* sf0  = fs + 1536;     // 256
    float* sf1  = fs + 1792;     // 256
    float* b3s  = fs + 2048;     // 4

    int tid = threadIdx.x, lane = tid & 31;
    int h = tid >> 8;            // half: 0=diffusion, 1=cnf
    int htid = tid & 255;
    int widh = htid >> 5;        // warp within half
    size_t row0 = (size_t)blockIdx.x * ROWS;

    // W2 transposed (Wt[n][k]) single fp16, both nets
    for (int i = tid; i < HID * HID; i += 512) {
        int k = i >> 7, n = i & 127;
        ((__half*)(sw + T_WDH))[n * 136 + k] = __float2half(dW2[i]);
        ((__half*)(sw + T_WCH))[n * 136 + k] = __float2half(cW2[i]);
    }
    if (tid < 128)      b2d[tid] = db2[tid];
    else if (tid < 256) b2c[tid - 128] = cb2[tid - 128];
    if (tid < 256) w3d[tid] = dW3[tid];
    else           w3c[tid - 256] = cW3[tid - 256];
    if (tid < 2)   { b3s[tid] = db3[tid]; b3s[2 + tid] = cb3[tid]; }
    if (tid < 256) {
        float zv = z0[row0 * 2 + tid];
        zsm[tid] = zv;
        out[row0 * 2 + tid] = zv;   // traj[0]
    }

    // per-thread layer1 constants (column fixed per thread)
    int cc = (htid & 63) * 2;
    const float* W1g = h ? cW1 : dW1;
    float w1aa = W1g[cc], w1ab = W1g[cc + 1];
    float w1ba = W1g[HID + cc], w1bb = W1g[HID + cc + 1];
    const float* prebase = (h ? g_cctx : g_dctx) + row0 * HID + cc;
    const float* tvg = h ? g_tvc : g_tvd;
    uint32_t* At = sw + (h ? T_AC : T_AD);
    const uint32_t* Wth = sw + (h ? T_WCH : T_WDH);
    const float* b2 = h ? b2c : b2d;
    const float* w3 = h ? w3c : w3d;
    float* st0 = h ? sf0 : su0;
    float* st1 = h ? sf1 : su1;
    int aw = (cc >> 1);
    __syncthreads();

    for (int s = 0; s < NSTEPS; ++s) {
        float2 tvv = *(const float2*)(tvg + s * HID + cc);
        float dt = g_dt[s], gsc = g_gs[s];
        float xi = 0.0f;
        if (tid < 256) xi = noise[(size_t)s * ((size_t)NPTS * 2) + row0 * 2 + tid];

        // layer1 for this half's net -> fp16 A tile
        {
            int r = htid >> 6;
#pragma unroll 4
            for (int k = 0; k < 32; ++k, r += 4) {
                float2 pv = *(const float2*)(prebase + r * HID);
                float za = zsm[2 * r], zb = zsm[2 * r + 1];
                float h0 = siluf(pv.x + tvv.x + za * w1aa + zb * w1ba);
                float h1 = siluf(pv.y + tvv.y + za * w1ab + zb * w1bb);
                uint32_t pk;
                asm("cvt.rn.f16x2.f32 %0,%1,%2;" : "=r"(pk) : "f"(h1), "f"(h0));
                At[r * LDAW + aw] = pk;
            }
        }
        asm volatile("bar.sync %0, 256;" :: "r"(1 + h) : "memory");

        net_pass(At, Wth, b2, w3, st0, st1, widh, lane);
        __syncthreads();

        if (tid < 256) {   // SDE update: 256 threads = 128 rows x 2 dims
            float au = su0[tid] + su1[tid] + b3s[tid & 1];
            float af = sf0[tid] + sf1[tid] + b3s[2 + (tid & 1)];
            size_t gi = row0 * 2 + tid;
            float zn = zsm[tid] + (af + au) * dt + xi * gsc;
            out[OUT_US + (size_t)s * ((size_t)NPTS * 2) + gi] = au;
            out[(size_t)(s + 1) * ((size_t)NPTS * 2) + gi]    = zn;
            zsm[tid] = zn;
        }
        __syncthreads();   // zsm visible, stages free for next step
    }
}

extern "C" void kernel_launch(void* const* d_in, const int* in_sizes, int n_in,
                              void* d_out, int out_size) {
    (void)in_sizes; (void)n_in; (void)out_size;
    const float* z0    = (const float*)d_in[0];
    const float* pctx  = (const float*)d_in[1];
    const float* cctx  = (const float*)d_in[2];
    const float* times = (const float*)d_in[3];
    const float* noise = (const float*)d_in[4];
    const float* freqs = (const float*)d_in[5];
    const float* dW1   = (const float*)d_in[6];
    const float* db1   = (const float*)d_in[7];
    const float* dW2   = (const float*)d_in[8];
    const float* db2   = (const float*)d_in[9];
    const float* dW3   = (const float*)d_in[10];
    const float* db3   = (const float*)d_in[11];
    const float* cW1   = (const float*)d_in[12];
    const float* cb1   = (const float*)d_in[13];
    const float* cW2   = (const float*)d_in[14];
    const float* cb2   = (const float*)d_in[15];
    const float* cW3   = (const float*)d_in[16];
    const float* cb3   = (const float*)d_in[17];
    const float* logd  = (const float*)d_in[18];
    float* out = (float*)d_out;

    const int CTX_SMEM = (HID * HID + 64 * AS_LD) * (int)sizeof(float);
    static int done = 0;
    if (!done) {
        cudaFuncSetAttribute(ctx_kernel, cudaFuncAttributeMaxDynamicSharedMemorySize, CTX_SMEM);
        cudaFuncSetAttribute(sde_mma_kernel, cudaFuncAttributeMaxDynamicSharedMemorySize, SDE_SMEM);
        done = 1;
    }
    step_const_kernel<<<NSTEPS, 128>>>(times, freqs, dW1, cW1, logd, out);
    ctx_kernel<<<NPTS / 64, 256, CTX_SMEM>>>(pctx, dW1, db1, 0);
    ctx_kernel<<<NPTS / 64, 256, CTX_SMEM>>>(cctx, cW1, cb1, 1);
    sde_mma_kernel<<<NPTS / ROWS, 512, SDE_SMEM>>>(z0, noise, dW1, dW2, db2, dW3, db3,
                                                   cW1, cW2, cb2, cW3, cb3, out);
}